// round 1
// baseline (speedup 1.0000x reference)
#include <cuda_runtime.h>
#include <math.h>

#define ND   768
#define NB   8
#define NCH  3
#define NMIX 5
#define NS   10
#define HH   10
#define PI2f 6.28318530717958647692f
#define ZITTERf 1e-4f
#define NPLANE (NB*NCH*NMIX)          // 120
#define PLANESZ ((size_t)ND*ND)       // 589824

// Scratch (static __device__ arrays: allowed; no runtime allocation)
__device__ float g_K[(size_t)NPLANE * ND * ND];   // K[(b*3+c)*5+m][i][j]  (~283 MB)
__device__ float g_feat[NPLANE * ND];             // feature[(b*3+c)*5+m][i]
__device__ float g_hmean[NB * NCH * HH];          // (8,30) flat = c*10+k
__device__ float g_w[NB * NCH * NMIX];            // w[b][c][m]

// ---------------------------------------------------------------------------
// Kernel 1: build K into scratch. Symmetric: only tiles tJ>=tI computed;
// off-diagonal tiles also write the mirrored tile.
// Block 256: tx=t&15 -> j quad (4 cols), ty=t>>4 -> 4 rows (ty, ty+16, +32, +48)
// ---------------------------------------------------------------------------
__global__ void __launch_bounds__(256) k1_build(const float* __restrict__ xc,
                                                const float* __restrict__ mu,
                                                const float* __restrict__ inv_std)
{
    int bc = blockIdx.z;                 // b*3 + c
    int b  = bc / NCH, c = bc - b*NCH;
    int tI = blockIdx.y, tJ = blockIdx.x;
    if (tJ < tI) return;

    __shared__ float sxi[64], sxj[64], sB[NMIX], sP[NMIX];
    int t = threadIdx.x;
    if (t < 64)        sxi[t]      = xc[(b*ND + tI*64 + t)      * NCH + c];
    else if (t < 128)  sxj[t-64]   = xc[(b*ND + tJ*64 + (t-64)) * NCH + c];
    else if (t < 128 + NMIX) {
        int m = t - 128;
        float s = inv_std[m];
        // exp(-0.5*(2pi)^2 * s^2 * dx^2) = exp2( B * dx^2 ),  B = -0.5*(2pi)^2*s^2*log2(e)
        sB[m] = -0.5f * PI2f * PI2f * 1.4426950408889634f * s * s;
        sP[m] = PI2f * mu[m];
    }
    __syncthreads();

    int tx = t & 15, ty = t >> 4;
    int j0 = tx * 4;
    float xj0 = sxj[j0], xj1 = sxj[j0+1], xj2 = sxj[j0+2], xj3 = sxj[j0+3];
    size_t planeBase = (size_t)(bc * NMIX) * PLANESZ;
    int gj = tJ*64 + j0;
    bool offdiag = (tI != tJ);

    #pragma unroll
    for (int ii = 0; ii < 4; ii++) {
        int i  = ty + ii*16;
        int gi = tI*64 + i;
        float xiv = sxi[i];
        float d0 = xiv - xj0, d1 = xiv - xj1, d2 = xiv - xj2, d3 = xiv - xj3;
        float q0 = d0*d0, q1 = d1*d1, q2 = d2*d2, q3 = d3*d3;
        #pragma unroll
        for (int m = 0; m < NMIX; m++) {
            float Bv = sB[m], Pv = sP[m];
            float4 v;
            v.x = exp2f(Bv*q0) * __cosf(Pv*d0);
            v.y = exp2f(Bv*q1) * __cosf(Pv*d1);
            v.z = exp2f(Bv*q2) * __cosf(Pv*d2);
            v.w = exp2f(Bv*q3) * __cosf(Pv*d3);
            size_t base = planeBase + (size_t)m * PLANESZ;
            *reinterpret_cast<float4*>(&g_K[base + (size_t)gi*ND + gj]) = v;
            if (offdiag) {   // mirrored (scattered STG.32 — L2 assembles the 16KB tile)
                g_K[base + (size_t)(gj+0)*ND + gi] = v.x;
                g_K[base + (size_t)(gj+1)*ND + gi] = v.y;
                g_K[base + (size_t)(gj+2)*ND + gi] = v.z;
                g_K[base + (size_t)(gj+3)*ND + gi] = v.w;
            }
        }
    }
}

// ---------------------------------------------------------------------------
// Kernel 2: feature[row] = sum_j K[row,:] * yc[b,:,c] + zitter*yc[b,i,c]
// One warp per row (row = plane*768 + i). 8 warps / block.
// ---------------------------------------------------------------------------
__global__ void __launch_bounds__(256) k2_matvec(const float* __restrict__ yc)
{
    int warp = threadIdx.x >> 5, lane = threadIdx.x & 31;
    int row  = blockIdx.x * 8 + warp;          // < 120*768
    int i    = row % ND;
    int pm   = row / ND;                       // plane = (b*3+c)*5+m
    int bc   = pm / NMIX;
    int b    = bc / NCH, c = bc - b*NCH;
    const float* Krow = &g_K[(size_t)pm * PLANESZ + (size_t)i * ND];
    float acc = 0.f;
    #pragma unroll 4
    for (int j = lane; j < ND; j += 32)
        acc += Krow[j] * yc[(b*ND + j)*NCH + c];
    #pragma unroll
    for (int o = 16; o; o >>= 1) acc += __shfl_xor_sync(0xffffffffu, acc, o);
    if (lane == 0)
        g_feat[row] = acc + ZITTERf * yc[(b*ND + i)*NCH + c];
}

// ---------------------------------------------------------------------------
// Kernel 3: hmean[b, c*10+k] = mean_i relu( [feature(5), yc] . W1[k] + b1[k] )
// One block per (b,c).
// ---------------------------------------------------------------------------
__global__ void __launch_bounds__(256) k3_hmean(const float* __restrict__ yc,
                                                const float* __restrict__ W1,
                                                const float* __restrict__ b1)
{
    int bc = blockIdx.x;
    int b  = bc / NCH, c = bc - b*NCH;
    __shared__ float sW[HH*6], sb[HH], sh[HH];
    int t = threadIdx.x;
    if (t < HH*6) sW[t] = W1[t];
    if (t < HH)   { sb[t] = b1[t]; sh[t] = 0.f; }
    __syncthreads();

    float hacc[HH];
    #pragma unroll
    for (int k = 0; k < HH; k++) hacc[k] = 0.f;

    for (int i = t; i < ND; i += 256) {
        float f[6];
        #pragma unroll
        for (int m = 0; m < NMIX; m++)
            f[m] = g_feat[(bc*NMIX + m)*ND + i];
        f[5] = yc[(b*ND + i)*NCH + c];
        #pragma unroll
        for (int k = 0; k < HH; k++) {
            float s = sb[k];
            #pragma unroll
            for (int u = 0; u < 6; u++) s += sW[k*6 + u] * f[u];
            hacc[k] += fmaxf(s, 0.f);
        }
    }
    #pragma unroll
    for (int k = 0; k < HH; k++) atomicAdd(&sh[k], hacc[k]);
    __syncthreads();
    if (t < HH)
        g_hmean[b*(NCH*HH) + c*HH + t] = sh[t] * (1.0f/ND);
}

// ---------------------------------------------------------------------------
// Kernel 4: small MLP (30->10->10->10->15) per batch + Gumbel-softmax -> w
// Single block of 128 threads.
// ---------------------------------------------------------------------------
__global__ void __launch_bounds__(128) k4_mlp_gumbel(
        const float* __restrict__ W2, const float* __restrict__ b2,
        const float* __restrict__ W3, const float* __restrict__ b3,
        const float* __restrict__ W4, const float* __restrict__ b4,
        const float* __restrict__ W5, const float* __restrict__ b5,
        const float* __restrict__ unif)
{
    __shared__ float ll[NB][NCH*NMIX];
    __shared__ float sw[NB][NCH*NMIX];
    int t = threadIdx.x;
    if (t < NB*NCH*NMIX) sw[t/(NCH*NMIX)][t%(NCH*NMIX)] = 0.f;

    if (t < NB) {
        int b = t;
        float hm[30], h2[HH], h3[HH], h4[HH];
        for (int u = 0; u < 30; u++) hm[u] = g_hmean[b*30 + u];
        #pragma unroll
        for (int k = 0; k < HH; k++) {
            float s = b2[k];
            for (int u = 0; u < 30; u++) s += W2[k*30 + u] * hm[u];
            h2[k] = fmaxf(s, 0.f);
        }
        #pragma unroll
        for (int k = 0; k < HH; k++) {
            float s = b3[k];
            #pragma unroll
            for (int u = 0; u < HH; u++) s += W3[k*HH + u] * h2[u];
            h3[k] = fmaxf(s, 0.f);
        }
        #pragma unroll
        for (int k = 0; k < HH; k++) {
            float s = b4[k];
            #pragma unroll
            for (int u = 0; u < HH; u++) s += W4[k*HH + u] * h3[u];
            h4[k] = fmaxf(s, 0.f);
        }
        #pragma unroll
        for (int n = 0; n < NCH*NMIX; n++) {
            float s = b5[n];
            #pragma unroll
            for (int k = 0; k < HH; k++) s += W5[n*HH + k] * h4[k];
            ll[b][n] = s;
        }
    }
    __syncthreads();

    if (t < NB*NS) {
        int b = t / NS, s = t % NS;
        for (int c = 0; c < NCH; c++) {
            float z[NMIX], mx = -1e30f;
            #pragma unroll
            for (int m = 0; m < NMIX; m++) {
                float u = unif[((b*NS + s)*NCH + c)*NMIX + m];
                float g = -logf(-logf(u + 1e-20f));
                z[m] = (g + ll[b][c*NMIX + m]) * 10.0f;   // 1/TEMP
                mx = fmaxf(mx, z[m]);
            }
            float sum = 0.f;
            #pragma unroll
            for (int m = 0; m < NMIX; m++) { z[m] = expf(z[m] - mx); sum += z[m]; }
            float inv = 1.0f / (sum * (float)NS);
            #pragma unroll
            for (int m = 0; m < NMIX; m++)
                atomicAdd(&sw[b][c*NMIX + m], z[m] * inv);
        }
    }
    __syncthreads();
    if (t < NB*NCH*NMIX)
        g_w[t] = sw[t/(NCH*NMIX)][t%(NCH*NMIX)];
}

// ---------------------------------------------------------------------------
// Kernel 5: weighted[b,i,j,c] = sum_m w[b,c,m]*K + diag(zitter + clip(likerr)^2)
// grid (3 j-chunks, nd rows, nb); 256 threads.
// ---------------------------------------------------------------------------
__global__ void __launch_bounds__(256) k5_weighted(float* __restrict__ out,
                                                   const float* __restrict__ likerr)
{
    int b = blockIdx.z, i = blockIdx.y;
    int j = blockIdx.x * 256 + threadIdx.x;
    __shared__ float sw[NCH*NMIX], sd[NCH];
    int t = threadIdx.x;
    if (t < NCH*NMIX) sw[t] = g_w[b*NCH*NMIX + t];
    if (t < NCH) {
        float l = fminf(fmaxf(likerr[t], 0.1f), 1.0f);
        sd[t] = ZITTERf + l*l;
    }
    __syncthreads();

    float o[NCH];
    #pragma unroll
    for (int c = 0; c < NCH; c++) {
        float acc = 0.f;
        #pragma unroll
        for (int m = 0; m < NMIX; m++)
            acc += sw[c*NMIX + m] *
                   g_K[((size_t)((b*NCH + c)*NMIX + m))*PLANESZ + (size_t)i*ND + j];
        if (i == j) acc += sd[c];
        o[c] = acc;
    }
    size_t ob = ((size_t)(b*ND + i)*ND + j) * NCH;
    out[ob + 0] = o[0];
    out[ob + 1] = o[1];
    out[ob + 2] = o[2];
}

// ---------------------------------------------------------------------------
extern "C" void kernel_launch(void* const* d_in, const int* in_sizes, int n_in,
                              void* d_out, int out_size)
{
    const float* xc      = (const float*)d_in[0];
    const float* yc      = (const float*)d_in[1];
    const float* mu      = (const float*)d_in[2];
    const float* inv_std = (const float*)d_in[3];
    const float* likerr  = (const float*)d_in[4];
    const float* unif    = (const float*)d_in[5];
    const float* W1 = (const float*)d_in[6];  const float* b1 = (const float*)d_in[7];
    const float* W2 = (const float*)d_in[8];  const float* b2 = (const float*)d_in[9];
    const float* W3 = (const float*)d_in[10]; const float* b3 = (const float*)d_in[11];
    const float* W4 = (const float*)d_in[12]; const float* b4 = (const float*)d_in[13];
    const float* W5 = (const float*)d_in[14]; const float* b5 = (const float*)d_in[15];
    float* out = (float*)d_out;

    k1_build  <<< dim3(ND/64, ND/64, NB*NCH), 256 >>>(xc, mu, inv_std);
    k2_matvec <<< (NPLANE*ND)/8, 256 >>>(yc);
    k3_hmean  <<< NB*NCH, 256 >>>(yc, W1, b1);
    k4_mlp_gumbel <<< 1, 128 >>>(W2, b2, W3, b3, W4, b4, W5, b5, unif);
    k5_weighted <<< dim3(ND/256, ND, NB), 256 >>>(out, likerr);
}

// round 2
// speedup vs baseline: 1.9029x; 1.9029x over previous
#include <cuda_runtime.h>
#include <math.h>

#define ND   768
#define NB   8
#define NCH  3
#define NMIX 5
#define NS   10
#define HH   10
#define PI2f 6.28318530717958647692f
#define ZITTERf 1e-4f
#define NPLANE (NB*NCH*NMIX)          // 120
#define PLANESZ ((size_t)ND*ND)       // 589824

__device__ float g_K[(size_t)NPLANE * ND * ND];   // ~283 MB scratch
__device__ float g_feat[NPLANE * ND];             // feature accumulators (atomics)
__device__ float g_hmean[NB * NCH * HH];
__device__ float g_w[NB * NCH * NMIX];

// ---------------------------------------------------------------------------
// Kernel 0: zero the feature accumulator (required every replay)
// ---------------------------------------------------------------------------
__global__ void k0_zero()
{
    int i = blockIdx.x * 256 + threadIdx.x;
    if (i < NPLANE * ND) g_feat[i] = 0.f;
}

// ---------------------------------------------------------------------------
// Kernel 1: build K (symmetric, upper-triangle tiles) + fused feature matvec.
//  - direct tile: STG.128, feature-I accumulated from registers
//  - mirror tile: staged in smem transpose (stride 65), written coalesced,
//    feature-J accumulated during the write-out pass
// Block 256: tx=t&15 -> j quad (4 cols), ty=t>>4 -> 4 rows (ty+16*ii)
// ---------------------------------------------------------------------------
__global__ void __launch_bounds__(256) k1_build(const float* __restrict__ xc,
                                                const float* __restrict__ yc,
                                                const float* __restrict__ mu,
                                                const float* __restrict__ inv_std)
{
    int bc = blockIdx.z;                 // b*3 + c
    int b  = bc / NCH, c = bc - b*NCH;
    int tI = blockIdx.y, tJ = blockIdx.x;
    if (tJ < tI) return;

    __shared__ float sxi[64], sxj[64], syi[64], syj[64], sB[NMIX], sP[NMIX];
    __shared__ float sT[64 * 65];        // transposed tile staging (16.6 KB)

    int t = threadIdx.x;
    if (t < 64) {
        int gi = tI*64 + t;
        sxi[t] = xc[(b*ND + gi)*NCH + c];
        syi[t] = yc[(b*ND + gi)*NCH + c];
    } else if (t < 128) {
        int j = t - 64, gj = tJ*64 + j;
        sxj[j] = xc[(b*ND + gj)*NCH + c];
        syj[j] = yc[(b*ND + gj)*NCH + c];
    } else if (t < 128 + NMIX) {
        int m = t - 128;
        float s = inv_std[m];
        sB[m] = -0.5f * PI2f * PI2f * 1.4426950408889634f * s * s;  // exp2 form
        sP[m] = PI2f * mu[m];
    }
    __syncthreads();

    int tx = t & 15, ty = t >> 4;
    int j0 = tx * 4;
    int gj0 = tJ*64 + j0;
    bool offdiag = (tI != tJ);
    int w = t >> 5, lane = t & 31;

    float xj[4], yj4[4];
    #pragma unroll
    for (int q = 0; q < 4; q++) { xj[q] = sxj[j0+q]; yj4[q] = syj[j0+q]; }

    float d[4][4];
    #pragma unroll
    for (int ii = 0; ii < 4; ii++) {
        float xiv = sxi[ty + ii*16];
        #pragma unroll
        for (int q = 0; q < 4; q++) d[ii][q] = xiv - xj[q];
    }

    float accI[4][NMIX];
    #pragma unroll
    for (int ii = 0; ii < 4; ii++)
        #pragma unroll
        for (int m = 0; m < NMIX; m++) accI[ii][m] = 0.f;

    #pragma unroll
    for (int m = 0; m < NMIX; m++) {
        float Bv = sB[m], Pv = sP[m];
        size_t mBase = (size_t)(bc*NMIX + m) * PLANESZ;

        #pragma unroll
        for (int ii = 0; ii < 4; ii++) {
            int i  = ty + ii*16;
            int gi = tI*64 + i;
            float d0 = d[ii][0], d1 = d[ii][1], d2 = d[ii][2], d3 = d[ii][3];
            float4 v;
            v.x = exp2f(Bv*d0*d0) * __cosf(Pv*d0);
            v.y = exp2f(Bv*d1*d1) * __cosf(Pv*d1);
            v.z = exp2f(Bv*d2*d2) * __cosf(Pv*d2);
            v.w = exp2f(Bv*d3*d3) * __cosf(Pv*d3);
            *reinterpret_cast<float4*>(&g_K[mBase + (size_t)gi*ND + gj0]) = v;
            accI[ii][m] += v.x*yj4[0] + v.y*yj4[1] + v.z*yj4[2] + v.w*yj4[3];
            if (offdiag) {
                sT[(j0+0)*65 + i] = v.x;
                sT[(j0+1)*65 + i] = v.y;
                sT[(j0+2)*65 + i] = v.z;
                sT[(j0+3)*65 + i] = v.w;
            }
        }

        if (offdiag) {
            __syncthreads();
            // mirror write: warp w covers rows 8w..8w+7, fully coalesced STG
            #pragma unroll
            for (int rr = 0; rr < 8; rr++) {
                int r  = w*8 + rr;            // local j row
                int gj = tJ*64 + r;
                float* dst = &g_K[mBase + (size_t)gj*ND + tI*64];
                float fj = 0.f;
                #pragma unroll
                for (int hh = 0; hh < 2; hh++) {
                    int col = lane + 32*hh;
                    float vv = sT[r*65 + col];
                    dst[col] = vv;
                    fj += vv * syi[col];
                }
                #pragma unroll
                for (int o = 16; o; o >>= 1)
                    fj += __shfl_xor_sync(0xffffffffu, fj, o);
                if (lane == 0)
                    atomicAdd(&g_feat[(bc*NMIX + m)*ND + gj], fj);
            }
            __syncthreads();
        }
    }

    // feature-I: reduce over the 16 j-lanes (tx), then atomic per row
    #pragma unroll
    for (int ii = 0; ii < 4; ii++) {
        #pragma unroll
        for (int m = 0; m < NMIX; m++) {
            float a = accI[ii][m];
            a += __shfl_xor_sync(0xffffffffu, a, 1);
            a += __shfl_xor_sync(0xffffffffu, a, 2);
            a += __shfl_xor_sync(0xffffffffu, a, 4);
            a += __shfl_xor_sync(0xffffffffu, a, 8);
            if (tx == 0)
                atomicAdd(&g_feat[(bc*NMIX + m)*ND + tI*64 + ty + ii*16], a);
        }
    }
}

// ---------------------------------------------------------------------------
// Kernel 3: hmean[b, c*10+k] = mean_i relu( [feat(5)+zitter*yc, yc] . W1[k] + b1[k] )
// ---------------------------------------------------------------------------
__global__ void __launch_bounds__(256) k3_hmean(const float* __restrict__ yc,
                                                const float* __restrict__ W1,
                                                const float* __restrict__ b1)
{
    int bc = blockIdx.x;
    int b  = bc / NCH, c = bc - b*NCH;
    __shared__ float sW[HH*6], sb[HH], sh[HH];
    int t = threadIdx.x;
    if (t < HH*6) sW[t] = W1[t];
    if (t < HH)   { sb[t] = b1[t]; sh[t] = 0.f; }
    __syncthreads();

    float hacc[HH];
    #pragma unroll
    for (int k = 0; k < HH; k++) hacc[k] = 0.f;

    for (int i = t; i < ND; i += 256) {
        float ycv = yc[(b*ND + i)*NCH + c];
        float f[6];
        #pragma unroll
        for (int m = 0; m < NMIX; m++)
            f[m] = g_feat[(bc*NMIX + m)*ND + i] + ZITTERf * ycv;
        f[5] = ycv;
        #pragma unroll
        for (int k = 0; k < HH; k++) {
            float s = sb[k];
            #pragma unroll
            for (int u = 0; u < 6; u++) s += sW[k*6 + u] * f[u];
            hacc[k] += fmaxf(s, 0.f);
        }
    }
    #pragma unroll
    for (int k = 0; k < HH; k++) atomicAdd(&sh[k], hacc[k]);
    __syncthreads();
    if (t < HH)
        g_hmean[b*(NCH*HH) + c*HH + t] = sh[t] * (1.0f/ND);
}

// ---------------------------------------------------------------------------
// Kernel 4: MLP (30->10->10->10->15) + Gumbel-softmax. Weights staged in smem,
// layers parallelized over (b,k); gumbel over 240 (b,s,c) threads.
// ---------------------------------------------------------------------------
__global__ void __launch_bounds__(256) k4_mlp_gumbel(
        const float* __restrict__ W2, const float* __restrict__ b2,
        const float* __restrict__ W3, const float* __restrict__ b3,
        const float* __restrict__ W4, const float* __restrict__ b4,
        const float* __restrict__ W5, const float* __restrict__ b5,
        const float* __restrict__ unif)
{
    __shared__ float w2[300], w3[100], w4[100], w5[150];
    __shared__ float sb2[HH], sb3[HH], sb4[HH], sb5[15];
    __shared__ float shm[NB][30], ha[NB][HH], hb[NB][HH], ll[NB][15], swacc[NB][15];
    int t = threadIdx.x;

    for (int u = t; u < 300; u += 256) w2[u] = W2[u];
    if (t < 100) { w3[t] = W3[t]; w4[t] = W4[t]; }
    if (t < 150) w5[t] = W5[t];
    if (t < HH)  { sb2[t] = b2[t]; sb3[t] = b3[t]; sb4[t] = b4[t]; }
    if (t < 15)  sb5[t] = b5[t];
    if (t < NB*30) shm[t/30][t%30] = g_hmean[t];
    if (t < NB*15) swacc[t/15][t%15] = 0.f;
    __syncthreads();

    if (t < NB*HH) {
        int b = t/HH, k = t%HH;
        float s = sb2[k];
        #pragma unroll
        for (int u = 0; u < 30; u++) s += w2[k*30+u] * shm[b][u];
        ha[b][k] = fmaxf(s, 0.f);
    }
    __syncthreads();
    if (t < NB*HH) {
        int b = t/HH, k = t%HH;
        float s = sb3[k];
        #pragma unroll
        for (int u = 0; u < HH; u++) s += w3[k*HH+u] * ha[b][u];
        hb[b][k] = fmaxf(s, 0.f);
    }
    __syncthreads();
    if (t < NB*HH) {
        int b = t/HH, k = t%HH;
        float s = sb4[k];
        #pragma unroll
        for (int u = 0; u < HH; u++) s += w4[k*HH+u] * hb[b][u];
        ha[b][k] = fmaxf(s, 0.f);
    }
    __syncthreads();
    if (t < NB*15) {
        int b = t/15, n = t%15;
        float s = sb5[n];
        #pragma unroll
        for (int k = 0; k < HH; k++) s += w5[n*HH+k] * ha[b][k];
        ll[b][n] = s;
    }
    __syncthreads();

    if (t < NB*NS*NCH) {          // 240 threads: one (b,s,c) each
        int b = t / (NS*NCH);
        int rem = t % (NS*NCH);
        int s_ = rem / NCH, c = rem % NCH;
        float z[NMIX], mx = -1e30f;
        #pragma unroll
        for (int m = 0; m < NMIX; m++) {
            float u = unif[((b*NS + s_)*NCH + c)*NMIX + m];
            float g = -logf(-logf(u + 1e-20f));
            z[m] = (g + ll[b][c*NMIX + m]) * 10.0f;   // 1/TEMP
            mx = fmaxf(mx, z[m]);
        }
        float sum = 0.f;
        #pragma unroll
        for (int m = 0; m < NMIX; m++) { z[m] = expf(z[m] - mx); sum += z[m]; }
        float inv = 1.0f / (sum * (float)NS);
        #pragma unroll
        for (int m = 0; m < NMIX; m++)
            atomicAdd(&swacc[b][c*NMIX + m], z[m] * inv);
    }
    __syncthreads();
    if (t < NB*NCH*NMIX)
        g_w[t] = swacc[t/(NCH*NMIX)][t%(NCH*NMIX)];
}

// ---------------------------------------------------------------------------
// Kernel 5: weighted[b,i,j,c] = sum_m w[b,c,m]*K + diag(zitter + clip(likerr)^2)
// ---------------------------------------------------------------------------
__global__ void __launch_bounds__(256) k5_weighted(float* __restrict__ out,
                                                   const float* __restrict__ likerr)
{
    int b = blockIdx.z, i = blockIdx.y;
    int j = blockIdx.x * 256 + threadIdx.x;
    __shared__ float sw[NCH*NMIX], sd[NCH];
    int t = threadIdx.x;
    if (t < NCH*NMIX) sw[t] = g_w[b*NCH*NMIX + t];
    if (t < NCH) {
        float l = fminf(fmaxf(likerr[t], 0.1f), 1.0f);
        sd[t] = ZITTERf + l*l;
    }
    __syncthreads();

    float o[NCH];
    #pragma unroll
    for (int c = 0; c < NCH; c++) {
        float acc = 0.f;
        #pragma unroll
        for (int m = 0; m < NMIX; m++)
            acc += sw[c*NMIX + m] *
                   g_K[((size_t)((b*NCH + c)*NMIX + m))*PLANESZ + (size_t)i*ND + j];
        if (i == j) acc += sd[c];
        o[c] = acc;
    }
    size_t ob = ((size_t)(b*ND + i)*ND + j) * NCH;
    out[ob + 0] = o[0];
    out[ob + 1] = o[1];
    out[ob + 2] = o[2];
}

// ---------------------------------------------------------------------------
extern "C" void kernel_launch(void* const* d_in, const int* in_sizes, int n_in,
                              void* d_out, int out_size)
{
    const float* xc      = (const float*)d_in[0];
    const float* yc      = (const float*)d_in[1];
    const float* mu      = (const float*)d_in[2];
    const float* inv_std = (const float*)d_in[3];
    const float* likerr  = (const float*)d_in[4];
    const float* unif    = (const float*)d_in[5];
    const float* W1 = (const float*)d_in[6];  const float* b1 = (const float*)d_in[7];
    const float* W2 = (const float*)d_in[8];  const float* b2 = (const float*)d_in[9];
    const float* W3 = (const float*)d_in[10]; const float* b3 = (const float*)d_in[11];
    const float* W4 = (const float*)d_in[12]; const float* b4 = (const float*)d_in[13];
    const float* W5 = (const float*)d_in[14]; const float* b5 = (const float*)d_in[15];
    float* out = (float*)d_out;

    k0_zero   <<< (NPLANE*ND + 255)/256, 256 >>>();
    k1_build  <<< dim3(ND/64, ND/64, NB*NCH), 256 >>>(xc, yc, mu, inv_std);
    k3_hmean  <<< NB*NCH, 256 >>>(yc, W1, b1);
    k4_mlp_gumbel <<< 1, 256 >>>(W2, b2, W3, b3, W4, b4, W5, b5, unif);
    k5_weighted <<< dim3(ND/256, ND, NB), 256 >>>(out, likerr);
}

// round 3
// speedup vs baseline: 2.8052x; 1.4741x over previous
#include <cuda_runtime.h>
#include <math.h>

#define ND   768
#define NB   8
#define NCH  3
#define NMIX 5
#define NS   10
#define HH   10
#define PI2f 6.28318530717958647692f
#define ZITTERf 1e-4f
#define NPLANE (NB*NCH*NMIX)          // 120

__device__ float g_feat[NPLANE * ND];             // feature accumulators (atomics)
__device__ float g_hmean[NB * NCH * HH];
__device__ float g_w[NB * NCH * NMIX];

// ---------------------------------------------------------------------------
// Kernel 0: zero the feature accumulator (required every graph replay)
// ---------------------------------------------------------------------------
__global__ void k0_zero()
{
    int i = blockIdx.x * 256 + threadIdx.x;
    if (i < NPLANE * ND) g_feat[i] = 0.f;
}

// ---------------------------------------------------------------------------
// Kernel A: feature[bc,m,i] = sum_j K_m(i,j)*yc[j]  (K recomputed, never stored)
// Upper-triangle 64x64 tiles; off-diag tiles also accumulate the mirrored
// contribution (featJ, dot with yc_i). No bulk global traffic at all.
// Block 256: tx=t&15 -> j quad, ty=t>>4 -> rows ty+16*ii
// ---------------------------------------------------------------------------
__global__ void __launch_bounds__(256) kA_feat(const float* __restrict__ xc,
                                               const float* __restrict__ yc,
                                               const float* __restrict__ mu,
                                               const float* __restrict__ inv_std)
{
    int bc = blockIdx.z;                 // b*3 + c
    int b  = bc / NCH, c = bc - b*NCH;
    int tI = blockIdx.y, tJ = blockIdx.x;
    if (tJ < tI) return;

    __shared__ float sxi[64], sxj[64], syi[64], syj[64], sB[NMIX], sP[NMIX];
    __shared__ float sFJ[NMIX * 64];

    int t = threadIdx.x;
    for (int u = t; u < NMIX*64; u += 256) sFJ[u] = 0.f;
    if (t < 64) {
        int gi = tI*64 + t;
        sxi[t] = xc[(b*ND + gi)*NCH + c];
        syi[t] = yc[(b*ND + gi)*NCH + c];
    } else if (t < 128) {
        int j = t - 64, gj = tJ*64 + j;
        sxj[j] = xc[(b*ND + gj)*NCH + c];
        syj[j] = yc[(b*ND + gj)*NCH + c];
    } else if (t < 128 + NMIX) {
        int m = t - 128;
        float s = inv_std[m];
        sB[m] = -0.5f * PI2f * PI2f * 1.4426950408889634f * s * s;  // exp2 form
        sP[m] = PI2f * mu[m];
    }
    __syncthreads();

    int tx = t & 15, ty = t >> 4;
    int lane = t & 31;
    int j0 = tx * 4;
    bool offdiag = (tI != tJ);

    float xj[4], yj4[4];
    #pragma unroll
    for (int q = 0; q < 4; q++) { xj[q] = sxj[j0+q]; yj4[q] = syj[j0+q]; }

    float accI[4][NMIX];
    float accJ[NMIX][4];
    #pragma unroll
    for (int ii = 0; ii < 4; ii++)
        #pragma unroll
        for (int m = 0; m < NMIX; m++) { accI[ii][m] = 0.f; accJ[m][ii] = 0.f; }

    #pragma unroll
    for (int ii = 0; ii < 4; ii++) {
        int i = ty + ii*16;
        float xiv = sxi[i], yiv = syi[i];
        float d0 = xiv - xj[0], d1 = xiv - xj[1], d2 = xiv - xj[2], d3 = xiv - xj[3];
        float e0 = d0*d0, e1 = d1*d1, e2 = d2*d2, e3 = d3*d3;
        #pragma unroll
        for (int m = 0; m < NMIX; m++) {
            float Bv = sB[m], Pv = sP[m];
            float v0 = exp2f(Bv*e0) * __cosf(Pv*d0);
            float v1 = exp2f(Bv*e1) * __cosf(Pv*d1);
            float v2 = exp2f(Bv*e2) * __cosf(Pv*d2);
            float v3 = exp2f(Bv*e3) * __cosf(Pv*d3);
            accI[ii][m] += v0*yj4[0] + v1*yj4[1] + v2*yj4[2] + v3*yj4[3];
            if (offdiag) {
                accJ[m][0] += v0*yiv; accJ[m][1] += v1*yiv;
                accJ[m][2] += v2*yiv; accJ[m][3] += v3*yiv;
            }
        }
    }

    // featI: reduce over 16 j-lanes (tx bits), atomic per row
    #pragma unroll
    for (int ii = 0; ii < 4; ii++) {
        #pragma unroll
        for (int m = 0; m < NMIX; m++) {
            float a = accI[ii][m];
            a += __shfl_xor_sync(0xffffffffu, a, 1);
            a += __shfl_xor_sync(0xffffffffu, a, 2);
            a += __shfl_xor_sync(0xffffffffu, a, 4);
            a += __shfl_xor_sync(0xffffffffu, a, 8);
            if (tx == 0)
                atomicAdd(&g_feat[(bc*NMIX + m)*ND + tI*64 + ty + ii*16], a);
        }
    }

    // featJ: pair-reduce (xor 16 merges the two ty's in a warp), smem, then global
    if (offdiag) {
        #pragma unroll
        for (int m = 0; m < NMIX; m++)
            #pragma unroll
            for (int q = 0; q < 4; q++) {
                float a = accJ[m][q];
                a += __shfl_xor_sync(0xffffffffu, a, 16);
                if (lane < 16)
                    atomicAdd(&sFJ[m*64 + j0 + q], a);
            }
        __syncthreads();
        if (t < 64) {
            #pragma unroll
            for (int m = 0; m < NMIX; m++)
                atomicAdd(&g_feat[(bc*NMIX + m)*ND + tJ*64 + t], sFJ[m*64 + t]);
        }
    }
}

// ---------------------------------------------------------------------------
// Kernel 3: hmean[b, c*10+k] = mean_i relu( [feat(5)+zitter*yc, yc] . W1[k] + b1[k] )
// ---------------------------------------------------------------------------
__global__ void __launch_bounds__(256) k3_hmean(const float* __restrict__ yc,
                                                const float* __restrict__ W1,
                                                const float* __restrict__ b1)
{
    int bc = blockIdx.x;
    int b  = bc / NCH, c = bc - b*NCH;
    __shared__ float sW[HH*6], sb[HH], sh[HH];
    int t = threadIdx.x;
    if (t < HH*6) sW[t] = W1[t];
    if (t < HH)   { sb[t] = b1[t]; sh[t] = 0.f; }
    __syncthreads();

    float hacc[HH];
    #pragma unroll
    for (int k = 0; k < HH; k++) hacc[k] = 0.f;

    for (int i = t; i < ND; i += 256) {
        float ycv = yc[(b*ND + i)*NCH + c];
        float f[6];
        #pragma unroll
        for (int m = 0; m < NMIX; m++)
            f[m] = g_feat[(bc*NMIX + m)*ND + i] + ZITTERf * ycv;
        f[5] = ycv;
        #pragma unroll
        for (int k = 0; k < HH; k++) {
            float s = sb[k];
            #pragma unroll
            for (int u = 0; u < 6; u++) s += sW[k*6 + u] * f[u];
            hacc[k] += fmaxf(s, 0.f);
        }
    }
    #pragma unroll
    for (int k = 0; k < HH; k++) atomicAdd(&sh[k], hacc[k]);
    __syncthreads();
    if (t < HH)
        g_hmean[b*(NCH*HH) + c*HH + t] = sh[t] * (1.0f/ND);
}

// ---------------------------------------------------------------------------
// Kernel 4: MLP (30->10->10->10->15) + Gumbel-softmax (fast-math intrinsics)
// ---------------------------------------------------------------------------
__global__ void __launch_bounds__(256) k4_mlp_gumbel(
        const float* __restrict__ W2, const float* __restrict__ b2,
        const float* __restrict__ W3, const float* __restrict__ b3,
        const float* __restrict__ W4, const float* __restrict__ b4,
        const float* __restrict__ W5, const float* __restrict__ b5,
        const float* __restrict__ unif)
{
    __shared__ float w2[300], w3[100], w4[100], w5[150];
    __shared__ float sb2[HH], sb3[HH], sb4[HH], sb5[15];
    __shared__ float shm[NB][30], ha[NB][HH], hb[NB][HH], ll[NB][15], swacc[NB][15];
    int t = threadIdx.x;

    for (int u = t; u < 300; u += 256) w2[u] = W2[u];
    if (t < 100) { w3[t] = W3[t]; w4[t] = W4[t]; }
    if (t < 150) w5[t] = W5[t];
    if (t < HH)  { sb2[t] = b2[t]; sb3[t] = b3[t]; sb4[t] = b4[t]; }
    if (t < 15)  sb5[t] = b5[t];
    if (t < NB*30) shm[t/30][t%30] = g_hmean[t];
    if (t < NB*15) swacc[t/15][t%15] = 0.f;
    __syncthreads();

    if (t < NB*HH) {
        int b = t/HH, k = t%HH;
        float s = sb2[k];
        #pragma unroll
        for (int u = 0; u < 30; u++) s += w2[k*30+u] * shm[b][u];
        ha[b][k] = fmaxf(s, 0.f);
    }
    __syncthreads();
    if (t < NB*HH) {
        int b = t/HH, k = t%HH;
        float s = sb3[k];
        #pragma unroll
        for (int u = 0; u < HH; u++) s += w3[k*HH+u] * ha[b][u];
        hb[b][k] = fmaxf(s, 0.f);
    }
    __syncthreads();
    if (t < NB*HH) {
        int b = t/HH, k = t%HH;
        float s = sb4[k];
        #pragma unroll
        for (int u = 0; u < HH; u++) s += w4[k*HH+u] * hb[b][u];
        ha[b][k] = fmaxf(s, 0.f);
    }
    __syncthreads();
    if (t < NB*15) {
        int b = t/15, n = t%15;
        float s = sb5[n];
        #pragma unroll
        for (int k = 0; k < HH; k++) s += w5[n*HH+k] * ha[b][k];
        ll[b][n] = s;
    }
    __syncthreads();

    if (t < NB*NS*NCH) {          // 240 threads: one (b,s,c) each
        int b = t / (NS*NCH);
        int rem = t % (NS*NCH);
        int s_ = rem / NCH, c = rem % NCH;
        float z[NMIX], mx = -1e30f;
        #pragma unroll
        for (int m = 0; m < NMIX; m++) {
            float u = unif[((b*NS + s_)*NCH + c)*NMIX + m];
            float g = -__logf(-__logf(u + 1e-20f));
            z[m] = (g + ll[b][c*NMIX + m]) * 10.0f;   // 1/TEMP
            mx = fmaxf(mx, z[m]);
        }
        float sum = 0.f;
        #pragma unroll
        for (int m = 0; m < NMIX; m++) { z[m] = __expf(z[m] - mx); sum += z[m]; }
        float inv = 1.0f / (sum * (float)NS);
        #pragma unroll
        for (int m = 0; m < NMIX; m++)
            atomicAdd(&swacc[b][c*NMIX + m], z[m] * inv);
    }
    __syncthreads();
    if (t < NB*NCH*NMIX)
        g_w[t] = swacc[t/(NCH*NMIX)][t%(NCH*NMIX)];
}

// ---------------------------------------------------------------------------
// Kernel B: out[b,i,j,c] = sum_m w[b,c,m]*K_cm(i,j) + diag — K recomputed.
// Full grid (no symmetry): all stores are aligned float4, zero K traffic.
// Block 256: tx=t&15 -> j quad, ty=t>>4 -> rows ty+16*ii
// ---------------------------------------------------------------------------
__global__ void __launch_bounds__(256) kB_out(float* __restrict__ out,
                                              const float* __restrict__ xc,
                                              const float* __restrict__ mu,
                                              const float* __restrict__ inv_std,
                                              const float* __restrict__ likerr)
{
    int b  = blockIdx.z;
    int tI = blockIdx.y, tJ = blockIdx.x;

    __shared__ float sxi[192], sxj[192], sB[NMIX], sP[NMIX], sw[NCH*NMIX], sd[NCH];
    int t = threadIdx.x;
    if (t < 192) {
        sxi[t] = xc[(size_t)(b*ND + tI*64)*NCH + t];   // 192 contiguous floats
        sxj[t] = xc[(size_t)(b*ND + tJ*64)*NCH + t];
    }
    if (t < NMIX) {
        float s = inv_std[t];
        sB[t] = -0.5f * PI2f * PI2f * 1.4426950408889634f * s * s;
        sP[t] = PI2f * mu[t];
    }
    if (t < NCH*NMIX) sw[t] = g_w[b*NCH*NMIX + t];
    if (t < NCH) {
        float l = fminf(fmaxf(likerr[t], 0.1f), 1.0f);
        sd[t] = ZITTERf + l*l;
    }
    __syncthreads();

    int tx = t & 15, ty = t >> 4;
    int j0 = tx * 4;
    int gj0 = tJ*64 + j0;

    float xj[NCH][4];
    #pragma unroll
    for (int c = 0; c < NCH; c++)
        #pragma unroll
        for (int q = 0; q < 4; q++)
            xj[c][q] = sxj[(j0+q)*NCH + c];

    #pragma unroll
    for (int ii = 0; ii < 4; ii++) {
        int i  = ty + ii*16;
        int gi = tI*64 + i;
        float vals[12];
        #pragma unroll
        for (int c = 0; c < NCH; c++) {
            float xiv = sxi[i*NCH + c];
            #pragma unroll
            for (int q = 0; q < 4; q++) {
                float d = xiv - xj[c][q];
                float e = d*d;
                float acc = 0.f;
                #pragma unroll
                for (int m = 0; m < NMIX; m++)
                    acc += sw[c*NMIX + m] * exp2f(sB[m]*e) * __cosf(sP[m]*d);
                if (gi == gj0 + q) acc += sd[c];
                vals[q*NCH + c] = acc;
            }
        }
        size_t base = ((size_t)(b*ND + gi)*ND + gj0) * NCH;   // *4B = 48-byte aligned
        float4* p = reinterpret_cast<float4*>(out + base);
        p[0] = make_float4(vals[0], vals[1], vals[2],  vals[3]);
        p[1] = make_float4(vals[4], vals[5], vals[6],  vals[7]);
        p[2] = make_float4(vals[8], vals[9], vals[10], vals[11]);
    }
}

// ---------------------------------------------------------------------------
extern "C" void kernel_launch(void* const* d_in, const int* in_sizes, int n_in,
                              void* d_out, int out_size)
{
    const float* xc      = (const float*)d_in[0];
    const float* yc      = (const float*)d_in[1];
    const float* mu      = (const float*)d_in[2];
    const float* inv_std = (const float*)d_in[3];
    const float* likerr  = (const float*)d_in[4];
    const float* unif    = (const float*)d_in[5];
    const float* W1 = (const float*)d_in[6];  const float* b1 = (const float*)d_in[7];
    const float* W2 = (const float*)d_in[8];  const float* b2 = (const float*)d_in[9];
    const float* W3 = (const float*)d_in[10]; const float* b3 = (const float*)d_in[11];
    const float* W4 = (const float*)d_in[12]; const float* b4 = (const float*)d_in[13];
    const float* W5 = (const float*)d_in[14]; const float* b5 = (const float*)d_in[15];
    float* out = (float*)d_out;

    k0_zero   <<< (NPLANE*ND + 255)/256, 256 >>>();
    kA_feat   <<< dim3(ND/64, ND/64, NB*NCH), 256 >>>(xc, yc, mu, inv_std);
    k3_hmean  <<< NB*NCH, 256 >>>(yc, W1, b1);
    k4_mlp_gumbel <<< 1, 256 >>>(W2, b2, W3, b3, W4, b4, W5, b5, unif);
    kB_out    <<< dim3(ND/64, ND/64, NB), 256 >>>(out, xc, mu, inv_std, likerr);
}

// round 4
// speedup vs baseline: 3.1786x; 1.1331x over previous
#include <cuda_runtime.h>
#include <math.h>

#define ND   768
#define NB   8
#define NCH  3
#define NMIX 5
#define NS   10
#define HH   10
#define PI2f 6.28318530717958647692f
#define ZITTERf 1e-4f
#define NPLANE (NB*NCH*NMIX)          // 120

__device__ float    g_feat[NPLANE * ND];   // zero-init; kA atomics; k34 reads then re-zeroes
__device__ float    g_hmean[NB * NCH * HH];
__device__ float    g_w[NB * NCH * NMIX];
__device__ unsigned g_ctr;                 // zero-init; k34 last-block counter (self-resetting)

// ---------------------------------------------------------------------------
// Kernel A: feature[bc,m,i] = sum_j K_m(i,j)*yc[j]  (K recomputed, never stored)
// Upper-triangle 64x64 tiles; off-diag tiles also accumulate mirrored featJ.
// ---------------------------------------------------------------------------
__global__ void __launch_bounds__(256) kA_feat(const float* __restrict__ xc,
                                               const float* __restrict__ yc,
                                               const float* __restrict__ mu,
                                               const float* __restrict__ inv_std)
{
    int bc = blockIdx.z;                 // b*3 + c
    int b  = bc / NCH, c = bc - b*NCH;
    int tI = blockIdx.y, tJ = blockIdx.x;
    if (tJ < tI) return;

    __shared__ float sxi[64], sxj[64], syi[64], syj[64], sB[NMIX], sP[NMIX];
    __shared__ float sFJ[NMIX * 64];

    int t = threadIdx.x;
    for (int u = t; u < NMIX*64; u += 256) sFJ[u] = 0.f;
    if (t < 64) {
        int gi = tI*64 + t;
        sxi[t] = xc[(b*ND + gi)*NCH + c];
        syi[t] = yc[(b*ND + gi)*NCH + c];
    } else if (t < 128) {
        int j = t - 64, gj = tJ*64 + j;
        sxj[j] = xc[(b*ND + gj)*NCH + c];
        syj[j] = yc[(b*ND + gj)*NCH + c];
    } else if (t < 128 + NMIX) {
        int m = t - 128;
        float s = inv_std[m];
        sB[m] = -0.5f * PI2f * PI2f * 1.4426950408889634f * s * s;  // exp2 form
        sP[m] = PI2f * mu[m];
    }
    __syncthreads();

    int tx = t & 15, ty = t >> 4;
    int lane = t & 31;
    int j0 = tx * 4;
    bool offdiag = (tI != tJ);

    float xj[4], yj4[4];
    #pragma unroll
    for (int q = 0; q < 4; q++) { xj[q] = sxj[j0+q]; yj4[q] = syj[j0+q]; }

    float accI[4][NMIX];
    float accJ[NMIX][4];
    #pragma unroll
    for (int ii = 0; ii < 4; ii++)
        #pragma unroll
        for (int m = 0; m < NMIX; m++) { accI[ii][m] = 0.f; accJ[m][ii] = 0.f; }

    #pragma unroll
    for (int ii = 0; ii < 4; ii++) {
        int i = ty + ii*16;
        float xiv = sxi[i], yiv = syi[i];
        float d0 = xiv - xj[0], d1 = xiv - xj[1], d2 = xiv - xj[2], d3 = xiv - xj[3];
        float e0 = d0*d0, e1 = d1*d1, e2 = d2*d2, e3 = d3*d3;
        #pragma unroll
        for (int m = 0; m < NMIX; m++) {
            float Bv = sB[m], Pv = sP[m];
            float v0 = exp2f(Bv*e0) * __cosf(Pv*d0);
            float v1 = exp2f(Bv*e1) * __cosf(Pv*d1);
            float v2 = exp2f(Bv*e2) * __cosf(Pv*d2);
            float v3 = exp2f(Bv*e3) * __cosf(Pv*d3);
            accI[ii][m] += v0*yj4[0] + v1*yj4[1] + v2*yj4[2] + v3*yj4[3];
            if (offdiag) {
                accJ[m][0] += v0*yiv; accJ[m][1] += v1*yiv;
                accJ[m][2] += v2*yiv; accJ[m][3] += v3*yiv;
            }
        }
    }

    #pragma unroll
    for (int ii = 0; ii < 4; ii++) {
        #pragma unroll
        for (int m = 0; m < NMIX; m++) {
            float a = accI[ii][m];
            a += __shfl_xor_sync(0xffffffffu, a, 1);
            a += __shfl_xor_sync(0xffffffffu, a, 2);
            a += __shfl_xor_sync(0xffffffffu, a, 4);
            a += __shfl_xor_sync(0xffffffffu, a, 8);
            if (tx == 0)
                atomicAdd(&g_feat[(bc*NMIX + m)*ND + tI*64 + ty + ii*16], a);
        }
    }

    if (offdiag) {
        #pragma unroll
        for (int m = 0; m < NMIX; m++)
            #pragma unroll
            for (int q = 0; q < 4; q++) {
                float a = accJ[m][q];
                a += __shfl_xor_sync(0xffffffffu, a, 16);
                if (lane < 16)
                    atomicAdd(&sFJ[m*64 + j0 + q], a);
            }
        __syncthreads();
        if (t < 64) {
            #pragma unroll
            for (int m = 0; m < NMIX; m++)
                atomicAdd(&g_feat[(bc*NMIX + m)*ND + tJ*64 + t], sFJ[m*64 + t]);
        }
    }
}

// ---------------------------------------------------------------------------
// Kernel 34: per-bc hmean (+ re-zero g_feat), then last block runs the MLP
// + Gumbel-softmax. Weights/unif prefetched by every block to hide latency.
// ---------------------------------------------------------------------------
__global__ void __launch_bounds__(256) k34_hmean_mlp(
        const float* __restrict__ yc,
        const float* __restrict__ W1, const float* __restrict__ b1,
        const float* __restrict__ W2, const float* __restrict__ b2,
        const float* __restrict__ W3, const float* __restrict__ b3,
        const float* __restrict__ W4, const float* __restrict__ b4,
        const float* __restrict__ W5, const float* __restrict__ b5,
        const float* __restrict__ unif)
{
    int bc = blockIdx.x;
    int b  = bc / NCH, c = bc - b*NCH;
    int t  = threadIdx.x;

    __shared__ float sW[HH*6], sb[HH], sh[HH];
    __shared__ float w2[300], w3[100], w4[100], w5[150];
    __shared__ float sb2[HH], sb3[HH], sb4[HH], sb5[15];
    __shared__ float su[NB*NS*NCH*NMIX];          // 1200 floats
    __shared__ float shm[NB][30], haL[NB][HH], hbL[NB][HH], ll[NB][15], swacc[NB][15];
    __shared__ bool  isLast;

    // prefetch everything the (potential) last block will need
    for (int u = t; u < 300; u += 256) w2[u] = W2[u];
    for (int u = t; u < 1200; u += 256) su[u] = unif[u];
    if (t < 100) { w3[t] = W3[t]; w4[t] = W4[t]; }
    if (t < 150) w5[t] = W5[t];
    if (t < HH)  { sb2[t] = b2[t]; sb3[t] = b3[t]; sb4[t] = b4[t]; }
    if (t < 15)  sb5[t] = b5[t];
    if (t < HH*6) sW[t] = W1[t];
    if (t < HH)  { sb[t] = b1[t]; sh[t] = 0.f; }
    __syncthreads();

    // ---- k3: hmean for this bc; zero g_feat behind us ----
    float hacc[HH];
    #pragma unroll
    for (int k = 0; k < HH; k++) hacc[k] = 0.f;

    for (int i = t; i < ND; i += 256) {
        float ycv = yc[(b*ND + i)*NCH + c];
        float f[6];
        #pragma unroll
        for (int m = 0; m < NMIX; m++) {
            int idx = (bc*NMIX + m)*ND + i;
            f[m] = g_feat[idx] + ZITTERf * ycv;
            g_feat[idx] = 0.f;                    // restore invariant for next replay
        }
        f[5] = ycv;
        #pragma unroll
        for (int k = 0; k < HH; k++) {
            float s = sb[k];
            #pragma unroll
            for (int u = 0; u < 6; u++) s += sW[k*6 + u] * f[u];
            hacc[k] += fmaxf(s, 0.f);
        }
    }
    #pragma unroll
    for (int k = 0; k < HH; k++) atomicAdd(&sh[k], hacc[k]);
    __syncthreads();
    if (t < HH)
        g_hmean[b*(NCH*HH) + c*HH + t] = sh[t] * (1.0f/ND);

    // ---- last-block takeover ----
    __threadfence();
    __syncthreads();
    if (t == 0) isLast = (atomicAdd(&g_ctr, 1u) == (unsigned)(NB*NCH - 1));
    __syncthreads();
    if (!isLast) return;
    if (t == 0) g_ctr = 0;                        // reset for next replay

    // read hmean written by other SMs (bypass potential stale L1 via volatile)
    if (t < NB*30) {
        const volatile float* hmv = g_hmean;
        shm[t/30][t%30] = hmv[t];
    }
    if (t < NB*15) swacc[t/15][t%15] = 0.f;
    __syncthreads();

    if (t < NB*HH) {
        int bb = t/HH, k = t%HH;
        float s = sb2[k];
        #pragma unroll
        for (int u = 0; u < 30; u++) s += w2[k*30+u] * shm[bb][u];
        haL[bb][k] = fmaxf(s, 0.f);
    }
    __syncthreads();
    if (t < NB*HH) {
        int bb = t/HH, k = t%HH;
        float s = sb3[k];
        #pragma unroll
        for (int u = 0; u < HH; u++) s += w3[k*HH+u] * haL[bb][u];
        hbL[bb][k] = fmaxf(s, 0.f);
    }
    __syncthreads();
    if (t < NB*HH) {
        int bb = t/HH, k = t%HH;
        float s = sb4[k];
        #pragma unroll
        for (int u = 0; u < HH; u++) s += w4[k*HH+u] * hbL[bb][u];
        haL[bb][k] = fmaxf(s, 0.f);
    }
    __syncthreads();
    if (t < NB*15) {
        int bb = t/15, n = t%15;
        float s = sb5[n];
        #pragma unroll
        for (int k = 0; k < HH; k++) s += w5[n*HH+k] * haL[bb][k];
        ll[bb][n] = s;
    }
    __syncthreads();

    if (t < NB*NS*NCH) {                          // 240 threads: one (b,s,c)
        int bb = t / (NS*NCH);
        int rem = t % (NS*NCH);
        int s_ = rem / NCH, cc = rem % NCH;
        float z[NMIX], mx = -1e30f;
        #pragma unroll
        for (int m = 0; m < NMIX; m++) {
            float u = su[((bb*NS + s_)*NCH + cc)*NMIX + m];
            float g = -__logf(-__logf(u + 1e-20f));
            z[m] = (g + ll[bb][cc*NMIX + m]) * 10.0f;   // 1/TEMP
            mx = fmaxf(mx, z[m]);
        }
        float sum = 0.f;
        #pragma unroll
        for (int m = 0; m < NMIX; m++) { z[m] = __expf(z[m] - mx); sum += z[m]; }
        float inv = 1.0f / (sum * (float)NS);
        #pragma unroll
        for (int m = 0; m < NMIX; m++)
            atomicAdd(&swacc[bb][cc*NMIX + m], z[m] * inv);
    }
    __syncthreads();
    if (t < NB*NCH*NMIX)
        g_w[t] = swacc[t/(NCH*NMIX)][t%(NCH*NMIX)];
}

// ---------------------------------------------------------------------------
// Kernel B: out[b,i,j,c] = sum_m w[b,c,m]*K_cm(i,j) + diag.  K recomputed,
// SYMMETRIC: only tiles tJ>=tI evaluated; mirror tile staged in smem and
// written as coalesced float4 rows.
// ---------------------------------------------------------------------------
#define MSTR 193   // smem mirror row stride (floats)

__global__ void __launch_bounds__(256) kB_out(float* __restrict__ out,
                                              const float* __restrict__ xc,
                                              const float* __restrict__ mu,
                                              const float* __restrict__ inv_std,
                                              const float* __restrict__ likerr)
{
    int b  = blockIdx.z;
    int tI = blockIdx.y, tJ = blockIdx.x;
    if (tJ < tI) return;
    bool offdiag = (tI != tJ);

    __shared__ float sxi[192], sxj[192], sB[NMIX], sP[NMIX], swv[NCH*NMIX], sd[NCH];
    __shared__ float sM[64 * MSTR];      // mirror staging: [j_local][i_local*3 + c]

    int t = threadIdx.x;
    if (t < 192) {
        sxi[t] = xc[(size_t)(b*ND + tI*64)*NCH + t];
        sxj[t] = xc[(size_t)(b*ND + tJ*64)*NCH + t];
    }
    if (t < NMIX) {
        float s = inv_std[t];
        sB[t] = -0.5f * PI2f * PI2f * 1.4426950408889634f * s * s;
        sP[t] = PI2f * mu[t];
    }
    if (t < NCH*NMIX) swv[t] = g_w[b*NCH*NMIX + t];
    if (t < NCH) {
        float l = fminf(fmaxf(likerr[t], 0.1f), 1.0f);
        sd[t] = ZITTERf + l*l;
    }
    __syncthreads();

    int tx = t & 15, ty = t >> 4;
    int j0 = tx * 4;
    int gj0 = tJ*64 + j0;

    float xj[NCH][4];
    #pragma unroll
    for (int c = 0; c < NCH; c++)
        #pragma unroll
        for (int q = 0; q < 4; q++)
            xj[c][q] = sxj[(j0+q)*NCH + c];

    #pragma unroll
    for (int ii = 0; ii < 4; ii++) {
        int i  = ty + ii*16;
        int gi = tI*64 + i;
        float vals[12];
        #pragma unroll
        for (int c = 0; c < NCH; c++) {
            float xiv = sxi[i*NCH + c];
            #pragma unroll
            for (int q = 0; q < 4; q++) {
                float d = xiv - xj[c][q];
                float e = d*d;
                float acc = 0.f;
                #pragma unroll
                for (int m = 0; m < NMIX; m++)
                    acc += swv[c*NMIX + m] * exp2f(sB[m]*e) * __cosf(sP[m]*d);
                vals[q*NCH + c] = acc;
            }
        }
        if (!offdiag) {        // diagonal tile: add noise diag where gi == gj
            #pragma unroll
            for (int q = 0; q < 4; q++)
                if (i == j0 + q)
                    #pragma unroll
                    for (int c = 0; c < NCH; c++) vals[q*NCH + c] += sd[c];
        }
        size_t base = ((size_t)(b*ND + gi)*ND + gj0) * NCH;
        float4* p = reinterpret_cast<float4*>(out + base);
        p[0] = make_float4(vals[0], vals[1], vals[2],  vals[3]);
        p[1] = make_float4(vals[4], vals[5], vals[6],  vals[7]);
        p[2] = make_float4(vals[8], vals[9], vals[10], vals[11]);
        if (offdiag) {         // stage transposed for the mirror tile
            #pragma unroll
            for (int q = 0; q < 4; q++)
                #pragma unroll
                for (int c = 0; c < NCH; c++)
                    sM[(j0+q)*MSTR + i*NCH + c] = vals[q*NCH + c];
        }
    }

    if (offdiag) {
        __syncthreads();
        // mirror write: 64 rows x 192 floats, coalesced float4 stores
        for (int f = t; f < 64*48; f += 256) {
            int r  = f / 48;           // local j row
            int c4 = f - r*48;         // float4 index within row
            int s0 = r*MSTR + c4*4;
            float4 v = make_float4(sM[s0], sM[s0+1], sM[s0+2], sM[s0+3]);
            reinterpret_cast<float4*>(
                out + ((size_t)(b*ND + tJ*64 + r)*ND + tI*64) * NCH)[c4] = v;
        }
    }
}

// ---------------------------------------------------------------------------
extern "C" void kernel_launch(void* const* d_in, const int* in_sizes, int n_in,
                              void* d_out, int out_size)
{
    const float* xc      = (const float*)d_in[0];
    const float* yc      = (const float*)d_in[1];
    const float* mu      = (const float*)d_in[2];
    const float* inv_std = (const float*)d_in[3];
    const float* likerr  = (const float*)d_in[4];
    const float* unif    = (const float*)d_in[5];
    const float* W1 = (const float*)d_in[6];  const float* b1 = (const float*)d_in[7];
    const float* W2 = (const float*)d_in[8];  const float* b2 = (const float*)d_in[9];
    const float* W3 = (const float*)d_in[10]; const float* b3 = (const float*)d_in[11];
    const float* W4 = (const float*)d_in[12]; const float* b4 = (const float*)d_in[13];
    const float* W5 = (const float*)d_in[14]; const float* b5 = (const float*)d_in[15];
    float* out = (float*)d_out;

    kA_feat <<< dim3(ND/64, ND/64, NB*NCH), 256 >>>(xc, yc, mu, inv_std);
    k34_hmean_mlp <<< NB*NCH, 256 >>>(yc, W1, b1, W2, b2, W3, b3, W4, b4, W5, b5, unif);
    kB_out  <<< dim3(ND/64, ND/64, NB), 256 >>>(out, xc, mu, inv_std, likerr);
}